// round 14
// baseline (speedup 1.0000x reference)
#include <cuda_runtime.h>

// out[i] = gen_map[x_gen[i]] + c*cs[i] + d*tdp[i], N = 8388608. DRAM-bound.
// v9 = v6 structure (adjacent-unit 128-bit reads + fused 256-bit evict_first
// stores) at VPT=4: 16 elems/thread, 192 B reads in flight, 2 fused stores.

#define BLOCK 256
#define VPT 4  // float4 units per thread -> 16 elems/thread

struct U64x4 { unsigned long long a, b, c, d; };

__device__ __forceinline__ void stg_ef_256(void* p, const U64x4& v) {
    asm volatile("st.global.L2::evict_first.v4.b64 [%0], {%1,%2,%3,%4};"
        :: "l"(p), "l"(v.a), "l"(v.b), "l"(v.c), "l"(v.d) : "memory");
}
__device__ __forceinline__ unsigned long long pack64(float lo, float hi) {
    return (unsigned long long)__float_as_uint(lo)
         | ((unsigned long long)__float_as_uint(hi) << 32);
}

// Fast path: NO bounds checks; grid exactly covers n4 float4-units.
__global__ void __launch_bounds__(BLOCK) fused_gather_axpy_v9(
    const int4* __restrict__ x_gen4,
    const float4* __restrict__ cs4,
    const float4* __restrict__ tdp4,
    const float* __restrict__ gen_map,
    const float* __restrict__ c_p,
    const float* __restrict__ d_p,
    float* __restrict__ out)
{
    __shared__ float s_map[1024];
    ((float4*)s_map)[threadIdx.x] = __ldg(&((const float4*)gen_map)[threadIdx.x]);

    const float c = __ldg(c_p);
    const float d = __ldg(d_p);

    // Each thread owns 4 ADJACENT float4 units (64 B contiguous per array).
    const long long base = ((long long)blockIdx.x * BLOCK + threadIdx.x) * VPT;

    // Front-batch all 12 128-bit streaming loads (192 B in flight).
    int4 g0 = __ldcg(&x_gen4[base]);
    int4 g1 = __ldcg(&x_gen4[base + 1]);
    int4 g2 = __ldcg(&x_gen4[base + 2]);
    int4 g3 = __ldcg(&x_gen4[base + 3]);
    float4 s0 = __ldcg(&cs4[base]);
    float4 s1 = __ldcg(&cs4[base + 1]);
    float4 s2 = __ldcg(&cs4[base + 2]);
    float4 s3 = __ldcg(&cs4[base + 3]);
    float4 t0 = __ldcg(&tdp4[base]);
    float4 t1 = __ldcg(&tdp4[base + 1]);
    float4 t2 = __ldcg(&tdp4[base + 2]);
    float4 t3 = __ldcg(&tdp4[base + 3]);

    __syncthreads();

    float r0  = s_map[g0.x] + c * s0.x + d * t0.x;
    float r1  = s_map[g0.y] + c * s0.y + d * t0.y;
    float r2  = s_map[g0.z] + c * s0.z + d * t0.z;
    float r3  = s_map[g0.w] + c * s0.w + d * t0.w;
    float r4  = s_map[g1.x] + c * s1.x + d * t1.x;
    float r5  = s_map[g1.y] + c * s1.y + d * t1.y;
    float r6  = s_map[g1.z] + c * s1.z + d * t1.z;
    float r7  = s_map[g1.w] + c * s1.w + d * t1.w;

    U64x4 oA;
    oA.a = pack64(r0, r1);
    oA.b = pack64(r2, r3);
    oA.c = pack64(r4, r5);
    oA.d = pack64(r6, r7);
    stg_ef_256(out + base * 4, oA);

    float r8  = s_map[g2.x] + c * s2.x + d * t2.x;
    float r9  = s_map[g2.y] + c * s2.y + d * t2.y;
    float r10 = s_map[g2.z] + c * s2.z + d * t2.z;
    float r11 = s_map[g2.w] + c * s2.w + d * t2.w;
    float r12 = s_map[g3.x] + c * s3.x + d * t3.x;
    float r13 = s_map[g3.y] + c * s3.y + d * t3.y;
    float r14 = s_map[g3.z] + c * s3.z + d * t3.z;
    float r15 = s_map[g3.w] + c * s3.w + d * t3.w;

    U64x4 oB;
    oB.a = pack64(r8, r9);
    oB.b = pack64(r10, r11);
    oB.c = pack64(r12, r13);
    oB.d = pack64(r14, r15);
    stg_ef_256(out + base * 4 + 8, oB);
}

// Generic fallback (any N), element-granular.
__global__ void fused_gather_axpy_generic(
    const int* __restrict__ x_gen,
    const float* __restrict__ cs,
    const float* __restrict__ tdp,
    const float* __restrict__ gen_map,
    const float* __restrict__ c_p,
    const float* __restrict__ d_p,
    float* __restrict__ out,
    int n)
{
    int i = blockIdx.x * blockDim.x + threadIdx.x;
    if (i >= n) return;
    float c = __ldg(c_p);
    float d = __ldg(d_p);
    out[i] = __ldg(&gen_map[x_gen[i]]) + c * cs[i] + d * tdp[i];
}

extern "C" void kernel_launch(void* const* d_in, const int* in_sizes, int n_in,
                              void* d_out, int out_size)
{
    const int*   x_gen   = (const int*)d_in[0];
    // d_in[1] = x_ix (unused)
    const float* cs      = (const float*)d_in[2];
    const float* tdp     = (const float*)d_in[3];
    const float* gen_map = (const float*)d_in[4];
    // d_in[5] = b (unused)
    const float* c_p     = (const float*)d_in[6];
    const float* d_p     = (const float*)d_in[7];
    float* out = (float*)d_out;

    const int n  = in_sizes[0];
    const int n4 = n / 4;
    const int units_per_block = BLOCK * VPT;

    if ((n % 4 == 0) && (n4 % units_per_block == 0)) {
        // Exact-cover fast path (holds for N = 8388608: 2048 blocks).
        fused_gather_axpy_v9<<<n4 / units_per_block, BLOCK>>>(
            (const int4*)x_gen, (const float4*)cs, (const float4*)tdp,
            gen_map, c_p, d_p, out);
    } else {
        fused_gather_axpy_generic<<<(n + 255) / 256, 256>>>(
            x_gen, cs, tdp, gen_map, c_p, d_p, out, n);
    }
}

// round 15
// speedup vs baseline: 1.0169x; 1.0169x over previous
#include <cuda_runtime.h>

// out[i] = gen_map[x_gen[i]] + c*cs[i] + d*tdp[i], N = 8388608. DRAM-bound.
// v10: fully-coalesced 128-bit reads (lane-strided: 4 full L1 lines/wavefront)
// + smem transpose (2 STS + syncwarp + 2 LDS per thread) so each lane owns 8
// contiguous output floats -> fused 256-bit evict_first store (R11 win),
// now also warp-contiguous (1024 B per store wavefront).

#define BLOCK 256
#define NWARP (BLOCK / 32)

struct U64x4 { unsigned long long a, b, c, d; };

__device__ __forceinline__ void stg_ef_256(void* p, const U64x4& v) {
    asm volatile("st.global.L2::evict_first.v4.b64 [%0], {%1,%2,%3,%4};"
        :: "l"(p), "l"(v.a), "l"(v.b), "l"(v.c), "l"(v.d) : "memory");
}
__device__ __forceinline__ unsigned long long pack64(float lo, float hi) {
    return (unsigned long long)__float_as_uint(lo)
         | ((unsigned long long)__float_as_uint(hi) << 32);
}

// Fast path: NO bounds checks; grid exactly covers n4 float4-units (n4 % 512 == 0).
__global__ void __launch_bounds__(BLOCK) fused_gather_axpy_v10(
    const int4* __restrict__ x_gen4,
    const float4* __restrict__ cs4,
    const float4* __restrict__ tdp4,
    const float* __restrict__ gen_map,
    const float* __restrict__ c_p,
    const float* __restrict__ d_p,
    float* __restrict__ out)
{
    __shared__ float  s_map[1024];
    __shared__ float4 xbuf[NWARP][64];   // per-warp exchange: 64 float4 = 1 KB

    ((float4*)s_map)[threadIdx.x] = __ldg(&((const float4*)gen_map)[threadIdx.x]);

    const float c = __ldg(c_p);
    const float d = __ldg(d_p);

    const int lane = threadIdx.x & 31;
    const int warp = threadIdx.x >> 5;
    // Warp owns 64 consecutive float4 units (1024 B per array).
    const long long wbase = ((long long)blockIdx.x * BLOCK + warp * 32) * 2;

    // Fully-coalesced reads: each instruction covers 512 contiguous bytes.
    const long long uA = wbase + lane;
    const long long uB = uA + 32;
    int4   gA = __ldcg(&x_gen4[uA]);
    int4   gB = __ldcg(&x_gen4[uB]);
    float4 sA = __ldcg(&cs4[uA]);
    float4 sB = __ldcg(&cs4[uB]);
    float4 tA = __ldcg(&tdp4[uA]);
    float4 tB = __ldcg(&tdp4[uB]);

    __syncthreads();   // s_map ready

    float4 rA, rB;
    rA.x = s_map[gA.x] + c * sA.x + d * tA.x;
    rA.y = s_map[gA.y] + c * sA.y + d * tA.y;
    rA.z = s_map[gA.z] + c * sA.z + d * tA.z;
    rA.w = s_map[gA.w] + c * sA.w + d * tA.w;
    rB.x = s_map[gB.x] + c * sB.x + d * tB.x;
    rB.y = s_map[gB.y] + c * sB.y + d * tB.y;
    rB.z = s_map[gB.z] + c * sB.z + d * tB.z;
    rB.w = s_map[gB.w] + c * sB.w + d * tB.w;

    // Smem transpose within the warp: unit (wbase+k) -> xbuf[warp][k].
    xbuf[warp][lane]      = rA;
    xbuf[warp][32 + lane] = rB;
    __syncwarp();

    // Lane l picks up units 2l, 2l+1 -> 8 contiguous output floats.
    float4 pA = xbuf[warp][2 * lane];
    float4 pB = xbuf[warp][2 * lane + 1];

    U64x4 o;
    o.a = pack64(pA.x, pA.y);
    o.b = pack64(pA.z, pA.w);
    o.c = pack64(pB.x, pB.y);
    o.d = pack64(pB.z, pB.w);
    stg_ef_256(out + (wbase + 2 * lane) * 4, o);
}

// Generic fallback (any N), element-granular.
__global__ void fused_gather_axpy_generic(
    const int* __restrict__ x_gen,
    const float* __restrict__ cs,
    const float* __restrict__ tdp,
    const float* __restrict__ gen_map,
    const float* __restrict__ c_p,
    const float* __restrict__ d_p,
    float* __restrict__ out,
    int n)
{
    int i = blockIdx.x * blockDim.x + threadIdx.x;
    if (i >= n) return;
    float c = __ldg(c_p);
    float d = __ldg(d_p);
    out[i] = __ldg(&gen_map[x_gen[i]]) + c * cs[i] + d * tdp[i];
}

extern "C" void kernel_launch(void* const* d_in, const int* in_sizes, int n_in,
                              void* d_out, int out_size)
{
    const int*   x_gen   = (const int*)d_in[0];
    // d_in[1] = x_ix (unused)
    const float* cs      = (const float*)d_in[2];
    const float* tdp     = (const float*)d_in[3];
    const float* gen_map = (const float*)d_in[4];
    // d_in[5] = b (unused)
    const float* c_p     = (const float*)d_in[6];
    const float* d_p     = (const float*)d_in[7];
    float* out = (float*)d_out;

    const int n  = in_sizes[0];
    const int n4 = n / 4;
    const int units_per_block = BLOCK * 2;

    if ((n % 4 == 0) && (n4 % units_per_block == 0)) {
        // Exact-cover fast path (holds for N = 8388608: 4096 blocks).
        fused_gather_axpy_v10<<<n4 / units_per_block, BLOCK>>>(
            (const int4*)x_gen, (const float4*)cs, (const float4*)tdp,
            gen_map, c_p, d_p, out);
    } else {
        fused_gather_axpy_generic<<<(n + 255) / 256, 256>>>(
            x_gen, cs, tdp, gen_map, c_p, d_p, out, n);
    }
}

// round 16
// speedup vs baseline: 1.0904x; 1.0723x over previous
#include <cuda_runtime.h>

// out[i] = gen_map[x_gen[i]] + c * x_max_clock_speed[i] + d * x_max_tdp[i]
// N = 8388608. DRAM-bound; steady-state ~7.1 TB/s (~88% of 8 TB/s spec) on a
// 3:1 R/W mixed stream. CONVERGED structure (best of 10 measured variants):
//  - exact-cover grid 4096 x 256, no bounds checks (N known divisible)
//  - gen_map (4 KB) staged in shared memory
//  - per-thread adjacent-unit layout: 2 x 128-bit __ldcg reads per array
//    (128-bit read granularity measured faster than 256-bit)
//  - single fused 256-bit L2::evict_first store per thread (the key win:
//    halves write transactions -> fewer DRAM bus turnarounds)
// Falsified alternatives: L2 evict_last pinning (R8/R9), persistent grid
// (R10), 256-bit reads (R12), shuffle exchange (R13), VPT=4 (R14), smem
// transpose (R15).

#define BLOCK 256
#define VPT 2  // float4 groups per thread -> 8 elems/thread

struct U64x4 { unsigned long long a, b, c, d; };

__device__ __forceinline__ void stg_ef_256(void* p, const U64x4& v) {
    asm volatile("st.global.L2::evict_first.v4.b64 [%0], {%1,%2,%3,%4};"
        :: "l"(p), "l"(v.a), "l"(v.b), "l"(v.c), "l"(v.d) : "memory");
}
__device__ __forceinline__ unsigned long long pack64(float lo, float hi) {
    return (unsigned long long)__float_as_uint(lo)
         | ((unsigned long long)__float_as_uint(hi) << 32);
}

// Fast path: NO bounds checks; grid exactly covers n4 float4-units.
__global__ void __launch_bounds__(BLOCK) fused_gather_axpy_v6(
    const int4* __restrict__ x_gen4,
    const float4* __restrict__ cs4,
    const float4* __restrict__ tdp4,
    const float* __restrict__ gen_map,
    const float* __restrict__ c_p,
    const float* __restrict__ d_p,
    float* __restrict__ out)
{
    __shared__ float s_map[1024];
    ((float4*)s_map)[threadIdx.x] = __ldg(&((const float4*)gen_map)[threadIdx.x]);

    const float c = __ldg(c_p);
    const float d = __ldg(d_p);

    // Each thread owns two ADJACENT float4 units so its 8 results are one
    // contiguous 32 B region -> single 256-bit store.
    const int base = (blockIdx.x * BLOCK + threadIdx.x) * VPT;

    // Front-batch all 6 128-bit streaming loads (MLP = 6).
    int4   g0 = __ldcg(&x_gen4[base]);
    int4   g1 = __ldcg(&x_gen4[base + 1]);
    float4 s0 = __ldcg(&cs4[base]);
    float4 s1 = __ldcg(&cs4[base + 1]);
    float4 t0 = __ldcg(&tdp4[base]);
    float4 t1 = __ldcg(&tdp4[base + 1]);

    __syncthreads();

    float r0 = s_map[g0.x] + c * s0.x + d * t0.x;
    float r1 = s_map[g0.y] + c * s0.y + d * t0.y;
    float r2 = s_map[g0.z] + c * s0.z + d * t0.z;
    float r3 = s_map[g0.w] + c * s0.w + d * t0.w;
    float r4 = s_map[g1.x] + c * s1.x + d * t1.x;
    float r5 = s_map[g1.y] + c * s1.y + d * t1.y;
    float r6 = s_map[g1.z] + c * s1.z + d * t1.z;
    float r7 = s_map[g1.w] + c * s1.w + d * t1.w;

    U64x4 o;
    o.a = pack64(r0, r1);
    o.b = pack64(r2, r3);
    o.c = pack64(r4, r5);
    o.d = pack64(r6, r7);
    stg_ef_256(out + (long long)base * 4, o);
}

// Generic fallback (any N), element-granular.
__global__ void fused_gather_axpy_generic(
    const int* __restrict__ x_gen,
    const float* __restrict__ cs,
    const float* __restrict__ tdp,
    const float* __restrict__ gen_map,
    const float* __restrict__ c_p,
    const float* __restrict__ d_p,
    float* __restrict__ out,
    int n)
{
    int i = blockIdx.x * blockDim.x + threadIdx.x;
    if (i >= n) return;
    float c = __ldg(c_p);
    float d = __ldg(d_p);
    out[i] = __ldg(&gen_map[x_gen[i]]) + c * cs[i] + d * tdp[i];
}

extern "C" void kernel_launch(void* const* d_in, const int* in_sizes, int n_in,
                              void* d_out, int out_size)
{
    const int*   x_gen   = (const int*)d_in[0];
    // d_in[1] = x_ix (unused)
    const float* cs      = (const float*)d_in[2];
    const float* tdp     = (const float*)d_in[3];
    const float* gen_map = (const float*)d_in[4];
    // d_in[5] = b (unused)
    const float* c_p     = (const float*)d_in[6];
    const float* d_p     = (const float*)d_in[7];
    float* out = (float*)d_out;

    const int n  = in_sizes[0];
    const int n4 = n / 4;
    const int units_per_block = BLOCK * VPT;

    if ((n % 4 == 0) && (n4 % units_per_block == 0)) {
        // Exact-cover fast path (holds for N = 8388608: 4096 blocks).
        fused_gather_axpy_v6<<<n4 / units_per_block, BLOCK>>>(
            (const int4*)x_gen, (const float4*)cs, (const float4*)tdp,
            gen_map, c_p, d_p, out);
    } else {
        fused_gather_axpy_generic<<<(n + 255) / 256, 256>>>(
            x_gen, cs, tdp, gen_map, c_p, d_p, out, n);
    }
}